// round 9
// baseline (speedup 1.0000x reference)
#include <cuda_runtime.h>
#include <cuda_bf16.h>
#include <math.h>
#include <stdint.h>

#define QLEN   1024
#define BSZ    4
#define DMODEL 1024
#define NHEAD  16
#define GHEADS 2
#define DHEAD  64
#define QKD    128
#define QKVOUT 1280
#define MROWS  4096
#define SCALE  0.125f
#define LN_EPS 1e-5f

// ---------------- scratch (device globals; no allocations allowed) ----------
__device__ float g_wheads[MROWS * QKVOUT];            // 4096 x 1280
__device__ float g_rk[QLEN * QKD];                    // 1024 x 128
__device__ float g_AC[BSZ * GHEADS * QLEN * QLEN];    // [bg][i][j]
__device__ float g_BD[BSZ * GHEADS * QLEN * QLEN];    // [bg][i][j] (pre-shift)
__device__ float g_avec[MROWS * DMODEL];              // attn_vec
__device__ float g_x[MROWS * DMODEL];                 // residual pre-LN

// bf16 hi/lo operand buffers (reused across the three GEMMs; stream-ordered)
__device__ __nv_bfloat16 g_bfA_hi[MROWS * DMODEL];
__device__ __nv_bfloat16 g_bfA_lo[MROWS * DMODEL];
__device__ __nv_bfloat16 g_bfB_hi[QKVOUT * DMODEL];
__device__ __nv_bfloat16 g_bfB_lo[QKVOUT * DMODEL];

// ---------------- helpers ----------------------------------------------------
__device__ __forceinline__ uint32_t smem_u32(const void* p) {
    uint32_t a;
    asm("{ .reg .u64 t; cvta.to.shared.u64 t, %1; cvt.u32.u64 %0, t; }"
        : "=r"(a) : "l"(p));
    return a;
}
__device__ __forceinline__ void ldm4(uint32_t* r, uint32_t addr) {
    asm volatile("ldmatrix.sync.aligned.m8n8.x4.shared.b16 {%0,%1,%2,%3}, [%4];"
                 : "=r"(r[0]), "=r"(r[1]), "=r"(r[2]), "=r"(r[3]) : "r"(addr));
}
__device__ __forceinline__ void mma16816(float* c, const uint32_t* a,
                                         uint32_t b0, uint32_t b1) {
    asm volatile(
        "mma.sync.aligned.m16n8k16.row.col.f32.bf16.bf16.f32 "
        "{%0,%1,%2,%3}, {%4,%5,%6,%7}, {%8,%9}, {%0,%1,%2,%3};"
        : "+f"(c[0]), "+f"(c[1]), "+f"(c[2]), "+f"(c[3])
        : "r"(a[0]), "r"(a[1]), "r"(a[2]), "r"(a[3]), "r"(b0), "r"(b1));
}
__device__ __forceinline__ void cp16(uint32_t saddr, const void* gaddr) {
    asm volatile("cp.async.cg.shared.global [%0], [%1], 16;\n"
                 :: "r"(saddr), "l"(gaddr) : "memory");
}

// ---------------- fp32 -> bf16 hi/lo split ----------------------------------
__global__ void __launch_bounds__(256) cvt_split(
    const float* __restrict__ x, __nv_bfloat16* __restrict__ hi,
    __nv_bfloat16* __restrict__ lo, int n)
{
    int i = (blockIdx.x * 256 + threadIdx.x) * 4;
    if (i >= n) return;
    float4 v = *(const float4*)(x + i);
    union { __nv_bfloat16 b[4]; uint2 u; } H, L;
    H.b[0] = __float2bfloat16_rn(v.x);
    H.b[1] = __float2bfloat16_rn(v.y);
    H.b[2] = __float2bfloat16_rn(v.z);
    H.b[3] = __float2bfloat16_rn(v.w);
    L.b[0] = __float2bfloat16_rn(v.x - __bfloat162float(H.b[0]));
    L.b[1] = __float2bfloat16_rn(v.y - __bfloat162float(H.b[1]));
    L.b[2] = __float2bfloat16_rn(v.z - __bfloat162float(H.b[2]));
    L.b[3] = __float2bfloat16_rn(v.w - __bfloat162float(H.b[3]));
    *(uint2*)(hi + i) = H.u;
    *(uint2*)(lo + i) = L.u;
}

// ---------------- HMMA split-bf16 NT GEMM, cp.async double-buffered ---------
// C[m,n] = sum_k A[m,k]*B[n,k] (+Dres). BM=BN=128, BK=32 bf16.
// 256 threads = 8 warps (2m x 4n), warp tile 64x32. K-major smem, stride 40.
#define LDSB  40
#define TILEE (128 * LDSB)                // bf16 elements per tile buffer
#define GEMM_SMEM (2 * 4 * TILEE * 2)     // 81920 bytes

__global__ void __launch_bounds__(256) mma_gemm(
    const __nv_bfloat16* __restrict__ Ahi, const __nv_bfloat16* __restrict__ Alo,
    const __nv_bfloat16* __restrict__ Bhi, const __nv_bfloat16* __restrict__ Blo,
    const float* __restrict__ Dres, float* __restrict__ C, int N_, int K)
{
    extern __shared__ __nv_bfloat16 gsm[];   // [2 stages][4 mats][TILEE]
    const uint32_t sbase = smem_u32(gsm);

    const int t = threadIdx.x;
    const int warp = t >> 5, lane = t & 31;
    const int wm = warp >> 2, wn = warp & 3;
    const int m0 = blockIdx.y * 128, n0 = blockIdx.x * 128;

    float acc[4][4][4];
    #pragma unroll
    for (int i = 0; i < 4; i++)
        #pragma unroll
        for (int j = 0; j < 4; j++)
            #pragma unroll
            for (int u = 0; u < 4; u++) acc[i][j][u] = 0.f;

    const int lrow = t >> 2;          // 0..63
    const int lseg = (t & 3) * 8;     // bf16 offset in BK=32

    const __nv_bfloat16* mat[4];
    mat[0] = Ahi + (size_t)m0 * K;
    mat[1] = Alo + (size_t)m0 * K;
    mat[2] = Bhi + (size_t)n0 * K;
    mat[3] = Blo + (size_t)n0 * K;

    const uint32_t so_b = ((uint32_t)lrow * LDSB + lseg) * 2;
    const uint32_t so_b2 = so_b + (uint32_t)64 * LDSB * 2;

    const uint32_t a_lane =
        ((uint32_t)(wm * 64 + (lane & 15)) * LDSB + (lane >> 4) * 8) * 2;
    const uint32_t b_lane =
        ((uint32_t)(wn * 32 + (lane & 7) + (lane >> 4) * 8) * LDSB +
         ((lane >> 3) & 1) * 8) * 2;

    const int NCH = K >> 5;

    // prologue: stage 0
    #pragma unroll
    for (int mi = 0; mi < 4; mi++) {
        const uint32_t mb = sbase + (uint32_t)mi * TILEE * 2;
        cp16(mb + so_b,  mat[mi] + (size_t)lrow * K + lseg);
        cp16(mb + so_b2, mat[mi] + (size_t)(lrow + 64) * K + lseg);
    }
    asm volatile("cp.async.commit_group;\n");

    for (int c = 0; c < NCH; c++) {
        if (c + 1 < NCH) {
            const int k0 = (c + 1) << 5;
            const uint32_t stoff = (uint32_t)(((c + 1) & 1) * 4) * TILEE * 2;
            #pragma unroll
            for (int mi = 0; mi < 4; mi++) {
                const uint32_t mb = sbase + stoff + (uint32_t)mi * TILEE * 2;
                cp16(mb + so_b,  mat[mi] + (size_t)lrow * K + k0 + lseg);
                cp16(mb + so_b2, mat[mi] + (size_t)(lrow + 64) * K + k0 + lseg);
            }
            asm volatile("cp.async.commit_group;\n");
            asm volatile("cp.async.wait_group 1;\n");
        } else {
            asm volatile("cp.async.wait_group 0;\n");
        }
        __syncthreads();

        const uint32_t stoff = (uint32_t)((c & 1) * 4) * TILEE * 2;
        const uint32_t bAh = sbase + stoff;
        const uint32_t bAl = bAh + TILEE * 2;
        const uint32_t bBh = bAl + TILEE * 2;
        const uint32_t bBl = bBh + TILEE * 2;

        #pragma unroll
        for (int s = 0; s < 2; s++) {
            const uint32_t ko = s * 32;
            uint32_t ah[4][4], al[4][4], bh[2][4], bl[2][4];
            #pragma unroll
            for (int mf = 0; mf < 4; mf++) {
                ldm4(ah[mf], bAh + a_lane + mf * 1280 + ko);
                ldm4(al[mf], bAl + a_lane + mf * 1280 + ko);
            }
            #pragma unroll
            for (int np = 0; np < 2; np++) {
                ldm4(bh[np], bBh + b_lane + np * 1280 + ko);
                ldm4(bl[np], bBl + b_lane + np * 1280 + ko);
            }
            #pragma unroll
            for (int mf = 0; mf < 4; mf++) {
                #pragma unroll
                for (int nf = 0; nf < 4; nf++) {
                    const int np = nf >> 1, h = (nf & 1) * 2;
                    mma16816(acc[mf][nf], ah[mf], bh[np][h], bh[np][h + 1]);
                    mma16816(acc[mf][nf], ah[mf], bl[np][h], bl[np][h + 1]);
                    mma16816(acc[mf][nf], al[mf], bh[np][h], bh[np][h + 1]);
                }
            }
        }
        __syncthreads();
    }

    const int crow0 = m0 + wm * 64 + (lane >> 2);
    const int ccol0 = n0 + wn * 32 + (lane & 3) * 2;
    #pragma unroll
    for (int mf = 0; mf < 4; mf++) {
        #pragma unroll
        for (int nf = 0; nf < 4; nf++) {
            const int gr = crow0 + mf * 16;
            const int gc = ccol0 + nf * 8;
            float2 v0 = make_float2(acc[mf][nf][0], acc[mf][nf][1]);
            float2 v1 = make_float2(acc[mf][nf][2], acc[mf][nf][3]);
            if (Dres) {
                float2 d0 = *(const float2*)(Dres + (size_t)gr * N_ + gc);
                float2 d1 = *(const float2*)(Dres + (size_t)(gr + 8) * N_ + gc);
                v0.x += d0.x; v0.y += d0.y;
                v1.x += d1.x; v1.y += d1.y;
            }
            *(float2*)(C + (size_t)gr * N_ + gc) = v0;
            *(float2*)(C + (size_t)(gr + 8) * N_ + gc) = v1;
        }
    }
}

// ---------------- AC / BD batched GEMM (K=64, fp32 FFMA) --------------------
__global__ void __launch_bounds__(256) acbd_kernel(
    const float* __restrict__ wheads, const float* __restrict__ rk,
    const float* __restrict__ bias, float* __restrict__ Cbase, int mode)
{
    __shared__ float As[16][132];
    __shared__ float Bs[16][132];
    const int bg = blockIdx.z;
    const int b = bg >> 1, g = bg & 1;
    const int bx = blockIdx.x, by = blockIdx.y;
    const int t  = threadIdx.x;
    const int tx = t & 15, ty = t >> 4;

    const float* Aoff = wheads + b * QKVOUT + g * 64;
    const float* Boff = mode ? (rk + g * 64)
                             : (wheads + b * QKVOUT + QKD + g * 64);
    const int lda = BSZ * QKVOUT;
    const int ldb = mode ? QKD : (BSZ * QKVOUT);
    const float* bb = bias + g * 64;

    float acc[8][8];
    #pragma unroll
    for (int i = 0; i < 8; i++)
        #pragma unroll
        for (int j = 0; j < 8; j++) acc[i][j] = 0.f;

    const int lrow = t >> 2;
    const int lk4  = (t & 3) * 4;

    for (int k0 = 0; k0 < 64; k0 += 16) {
        float4 bias4 = *(const float4*)(bb + k0 + lk4);
        #pragma unroll
        for (int rr = 0; rr < 2; rr++) {
            int m = lrow + rr * 64;
            int gm = by * 128 + m;
            float4 a = *(const float4*)(Aoff + (size_t)gm * lda + k0 + lk4);
            As[lk4 + 0][m] = a.x + bias4.x; As[lk4 + 1][m] = a.y + bias4.y;
            As[lk4 + 2][m] = a.z + bias4.z; As[lk4 + 3][m] = a.w + bias4.w;
            int gn = bx * 128 + m;
            float4 bv = *(const float4*)(Boff + (size_t)gn * ldb + k0 + lk4);
            Bs[lk4 + 0][m] = bv.x; Bs[lk4 + 1][m] = bv.y;
            Bs[lk4 + 2][m] = bv.z; Bs[lk4 + 3][m] = bv.w;
        }
        __syncthreads();
        #pragma unroll
        for (int kk = 0; kk < 16; kk++) {
            float ar[8], br[8];
            #pragma unroll
            for (int u = 0; u < 8; u++) ar[u] = As[kk][ty * 8 + u];
            #pragma unroll
            for (int u = 0; u < 8; u++) br[u] = Bs[kk][tx * 8 + u];
            #pragma unroll
            for (int i = 0; i < 8; i++)
                #pragma unroll
                for (int j = 0; j < 8; j++) acc[i][j] += ar[i] * br[j];
        }
        __syncthreads();
    }
    float* C = Cbase + (size_t)bg * QLEN * QLEN;
    const int mbase = by * 128 + ty * 8;
    const int nbase = bx * 128 + tx * 8;
    #pragma unroll
    for (int i = 0; i < 8; i++) {
        size_t roff = (size_t)(mbase + i) * QLEN + nbase;
        #pragma unroll
        for (int j0 = 0; j0 < 8; j0 += 4) {
            float4 o;
            o.x = acc[i][j0 + 0]; o.y = acc[i][j0 + 1];
            o.z = acc[i][j0 + 2]; o.w = acc[i][j0 + 3];
            *(float4*)(C + roff + j0) = o;
        }
    }
}

// ---------------- flash-style attention -------------------------------------
// grid (64 i-tiles of 16 rows, 8 bg), 256 threads. All 8 heads of the group
// share AC/BD/masks reads. Online softmax over j-tiles of 128, then PV.
// smem: S[8h][16r][132] + M/L/F[8][16].
#define SSTR   132
#define S_H    (16 * SSTR)                 // per-head stride (floats)
#define ATTN_SMEM ((8 * S_H + 3 * 128) * 4)

__global__ void __launch_bounds__(256) attn_kernel(
    const float* __restrict__ AC, const float* __restrict__ BD,
    const float* __restrict__ masks, const float* __restrict__ mproj,
    const float* __restrict__ wheads, float* __restrict__ avec)
{
    extern __shared__ float sm[];
    float* S = sm;                         // 8 * S_H
    float* Mx = sm + 8 * S_H;              // [8][16]
    float* Ls = Mx + 128;                  // [8][16]
    float* Fs = Ls + 128;                  // [8][16]

    const int bg = blockIdx.y;
    const int b = bg >> 1, g = bg & 1;
    const int i0 = blockIdx.x * 16;
    const int t = threadIdx.x;
    const int lane = t & 31;

    // score-phase mapping
    const int rsc = t >> 4;                // 0..15
    const int csc = t & 15;                // 0..15
    // PV mapping
    const int warp = t >> 5;
    const int rg = warp & 1, hq = warp >> 1;
    const int rr = lane >> 2, dq = lane & 3;
    const int rpv = rg * 8 + rr;
    const int dbase = dq * 16;

    float mp0[8], mp1[8], mp2[8];
    #pragma unroll
    for (int hh = 0; hh < 8; hh++) {
        const int h = g * 8 + hh;
        mp0[hh] = mproj[0 * NHEAD + h];
        mp1[hh] = mproj[1 * NHEAD + h];
        mp2[hh] = mproj[2 * NHEAD + h];
    }

    if (t < 128) { Mx[t] = -1e30f; Ls[t] = 0.f; }
    __syncthreads();

    float acc[2][16];
    #pragma unroll
    for (int hh = 0; hh < 2; hh++)
        #pragma unroll
        for (int u = 0; u < 16; u++) acc[hh][u] = 0.f;

    const float* acrow = AC + ((size_t)bg * QLEN + (i0 + rsc)) * QLEN;
    const float* bdbase = BD + (size_t)bg * QLEN * QLEN;
    const int i = i0 + rsc;

    for (int j0 = 0; j0 < QLEN; j0 += 128) {
        // ---- scores for 8 heads ----
        float tmax[8];
        #pragma unroll
        for (int hh = 0; hh < 8; hh++) tmax[hh] = -1e30f;

        #pragma unroll
        for (int k = 0; k < 8; k++) {
            const int jl = csc + k * 16;
            const int jg = j0 + jl;
            float ac = acrow[jg];
            unsigned s  = (unsigned)(i + 1) * 1024u + (unsigned)jg;
            unsigned i2 = s / 1025u;
            unsigned j2 = s - i2 * 1025u;
            float bd = (j2 == 0u) ? 0.f : bdbase[(size_t)i2 * QLEN + (j2 - 1u)];
            const float* mrow = masks + ((size_t)i * QLEN + jg) * 3;
            float m0 = mrow[0], m1 = mrow[1], m2 = mrow[2];
            float base = (ac + bd) * SCALE;
            #pragma unroll
            for (int hh = 0; hh < 8; hh++) {
                float v = base * (m0 * mp0[hh] + m1 * mp1[hh] + m2 * mp2[hh]);
                S[hh * S_H + rsc * SSTR + jl] = v;
                tmax[hh] = fmaxf(tmax[hh], v);
            }
        }
        // 16-lane group max reduce
        #pragma unroll
        for (int o = 8; o > 0; o >>= 1)
            #pragma unroll
            for (int hh = 0; hh < 8; hh++)
                tmax[hh] = fmaxf(tmax[hh], __shfl_xor_sync(0xffffffffu, tmax[hh], o));
        if ((lane & 15) == 0) {
            #pragma unroll
            for (int hh = 0; hh < 8; hh++) {
                float mo = Mx[hh * 16 + rsc];
                float mn = fmaxf(mo, tmax[hh]);
                Fs[hh * 16 + rsc] = __expf(mo - mn);
                Mx[hh * 16 + rsc] = mn;
            }
        }
        __syncthreads();

        // ---- exponentiate + running sum ----
        float tsum[8];
        #pragma unroll
        for (int hh = 0; hh < 8; hh++) tsum[hh] = 0.f;
        #pragma unroll
        for (int hh = 0; hh < 8; hh++) {
            const float mh = Mx[hh * 16 + rsc];
            #pragma unroll
            for (int k = 0; k < 8; k++) {
                const int jl = csc + k * 16;
                float e = __expf(S[hh * S_H + rsc * SSTR + jl] - mh);
                S[hh * S_H + rsc * SSTR + jl] = e;
                tsum[hh] += e;
            }
        }
        #pragma unroll
        for (int o = 8; o > 0; o >>= 1)
            #pragma unroll
            for (int hh = 0; hh < 8; hh++)
                tsum[hh] += __shfl_xor_sync(0xffffffffu, tsum[hh], o);
        if ((lane & 15) == 0) {
            #pragma unroll
            for (int hh = 0; hh < 8; hh++)
                Ls[hh * 16 + rsc] = Ls[hh * 16 + rsc] * Fs[hh * 16 + rsc] + tsum[hh];
        }
        __syncthreads();

        // ---- PV accumulate (warp = 8 rows x 16 cols, 2 heads) ----
        #pragma unroll
        for (int hh = 0; hh < 2; hh++) {
            const int h = hq * 2 + hh;
            const float f = Fs[h * 16 + rpv];
            #pragma unroll
            for (int u = 0; u < 16; u++) acc[hh][u] *= f;
            const float* Vb = wheads + (size_t)b * QKVOUT + 2 * QKD +
                              (g * 8 + h) * 64 + dbase;
            const float* Sp = S + h * S_H + rpv * SSTR;
            #pragma unroll 4
            for (int j = 0; j < 128; j++) {
                float p = Sp[j];
                const float* vr = Vb + (size_t)(j0 + j) * (BSZ * QKVOUT);
                float4 v0 = *(const float4*)(vr);
                float4 v1 = *(const float4*)(vr + 4);
                float4 v2 = *(const float4*)(vr + 8);
                float4 v3 = *(const float4*)(vr + 12);
                acc[hh][0]  += p * v0.x; acc[hh][1]  += p * v0.y;
                acc[hh][2]  += p * v0.z; acc[hh][3]  += p * v0.w;
                acc[hh][4]  += p * v1.x; acc[hh][5]  += p * v1.y;
                acc[hh][6]  += p * v1.z; acc[hh][7]  += p * v1.w;
                acc[hh][8]  += p * v2.x; acc[hh][9]  += p * v2.y;
                acc[hh][10] += p * v2.z; acc[hh][11] += p * v2.w;
                acc[hh][12] += p * v3.x; acc[hh][13] += p * v3.y;
                acc[hh][14] += p * v3.z; acc[hh][15] += p * v3.w;
            }
        }
        __syncthreads();
    }

    // ---- write out ----
    #pragma unroll
    for (int hh = 0; hh < 2; hh++) {
        const int h = hq * 2 + hh;
        const float inv = 1.f / Ls[h * 16 + rpv];
        const int iglob = i0 + rpv;
        float* op = avec + ((size_t)(iglob * BSZ + b) * NHEAD + (g * 8 + h)) * 64
                    + dbase;
        #pragma unroll
        for (int u = 0; u < 4; u++) {
            float4 o;
            o.x = acc[hh][u * 4 + 0] * inv;
            o.y = acc[hh][u * 4 + 1] * inv;
            o.z = acc[hh][u * 4 + 2] * inv;
            o.w = acc[hh][u * 4 + 3] * inv;
            *(float4*)(op + u * 4) = o;
        }
    }
}

// ---------------- LayerNorm over rows of g_x --------------------------------
__global__ void __launch_bounds__(256) ln_kernel(
    const float* __restrict__ X, const float* __restrict__ gamma,
    const float* __restrict__ beta, float* __restrict__ out)
{
    const int row = blockIdx.x;
    const int t = threadIdx.x;
    const float4* x4 = (const float4*)(X + (size_t)row * DMODEL);
    float4 v = x4[t];
    float s  = v.x + v.y + v.z + v.w;
    float sq = v.x * v.x + v.y * v.y + v.z * v.z + v.w * v.w;
    #pragma unroll
    for (int o = 16; o > 0; o >>= 1) {
        s  += __shfl_xor_sync(0xffffffffu, s,  o);
        sq += __shfl_xor_sync(0xffffffffu, sq, o);
    }
    __shared__ float ssum[8], ssq[8];
    __shared__ float smu, srstd;
    if ((t & 31) == 0) { ssum[t >> 5] = s; ssq[t >> 5] = sq; }
    __syncthreads();
    if (t == 0) {
        float ts = 0.f, tq = 0.f;
        #pragma unroll
        for (int k = 0; k < 8; k++) { ts += ssum[k]; tq += ssq[k]; }
        float mu = ts * (1.f / DMODEL);
        float var = tq * (1.f / DMODEL) - mu * mu;
        smu = mu;
        srstd = rsqrtf(var + LN_EPS);
    }
    __syncthreads();
    float mu = smu, rstd = srstd;
    float4 gm = ((const float4*)gamma)[t];
    float4 bt = ((const float4*)beta)[t];
    float4 o;
    o.x = (v.x - mu) * rstd * gm.x + bt.x;
    o.y = (v.y - mu) * rstd * gm.y + bt.y;
    o.z = (v.z - mu) * rstd * gm.z + bt.z;
    o.w = (v.w - mu) * rstd * gm.w + bt.w;
    ((float4*)(out + (size_t)row * DMODEL))[t] = o;
}

// ---------------- launch ----------------------------------------------------
extern "C" void kernel_launch(void* const* d_in, const int* in_sizes, int n_in,
                              void* d_out, int out_size)
{
    const float* w     = (const float*)d_in[0];
    const float* r     = (const float*)d_in[1];
    const float* rwb   = (const float*)d_in[2];
    const float* rrb   = (const float*)d_in[3];
    const float* masks = (const float*)d_in[4];
    const float* Wqkv  = (const float*)d_in[5];
    const float* Wr    = (const float*)d_in[6];
    const float* mproj = (const float*)d_in[7];
    const float* Wo    = (const float*)d_in[8];
    const float* gamma = (const float*)d_in[9];
    const float* beta  = (const float*)d_in[10];
    float* out = (float*)d_out;

    float *wheads, *rkp, *acp, *bdp, *avp, *xp;
    cudaGetSymbolAddress((void**)&wheads, g_wheads);
    cudaGetSymbolAddress((void**)&rkp,    g_rk);
    cudaGetSymbolAddress((void**)&acp,    g_AC);
    cudaGetSymbolAddress((void**)&bdp,    g_BD);
    cudaGetSymbolAddress((void**)&avp,    g_avec);
    cudaGetSymbolAddress((void**)&xp,     g_x);

    __nv_bfloat16 *Ah, *Al, *Bh, *Bl;
    cudaGetSymbolAddress((void**)&Ah, g_bfA_hi);
    cudaGetSymbolAddress((void**)&Al, g_bfA_lo);
    cudaGetSymbolAddress((void**)&Bh, g_bfB_hi);
    cudaGetSymbolAddress((void**)&Bl, g_bfB_lo);

    cudaFuncSetAttribute(mma_gemm,
                         cudaFuncAttributeMaxDynamicSharedMemorySize, GEMM_SMEM);
    cudaFuncSetAttribute(attn_kernel,
                         cudaFuncAttributeMaxDynamicSharedMemorySize, ATTN_SMEM);

    // 1) w_heads = w @ W_qkv^T
    cvt_split<<<(MROWS * DMODEL) / 1024, 256>>>(w, Ah, Al, MROWS * DMODEL);
    cvt_split<<<(QKVOUT * DMODEL) / 1024, 256>>>(Wqkv, Bh, Bl, QKVOUT * DMODEL);
    mma_gemm<<<dim3(QKVOUT / 128, MROWS / 128), 256, GEMM_SMEM>>>(
        Ah, Al, Bh, Bl, nullptr, wheads, QKVOUT, DMODEL);

    // 2) r_head_k = r @ W_r^T
    cvt_split<<<(QLEN * DMODEL) / 1024, 256>>>(r, Ah, Al, QLEN * DMODEL);
    cvt_split<<<(QKD * DMODEL) / 1024, 256>>>(Wr, Bh, Bl, QKD * DMODEL);
    mma_gemm<<<dim3(QKD / 128, QLEN / 128), 256, GEMM_SMEM>>>(
        Ah, Al, Bh, Bl, nullptr, rkp, QKD, DMODEL);

    // 3) AC, BD (pre-shift)
    acbd_kernel<<<dim3(8, 8, BSZ * GHEADS), 256>>>(wheads, rkp, rwb, acp, 0);
    acbd_kernel<<<dim3(8, 8, BSZ * GHEADS), 256>>>(wheads, rkp, rrb, bdp, 1);

    // 4) flash-style rel_shift + mask + softmax + P@V (8 heads/block shared)
    attn_kernel<<<dim3(QLEN / 16, BSZ * GHEADS), 256, ATTN_SMEM>>>(
        acp, bdp, masks, mproj, wheads, avp);

    // 5) x = attn_vec @ W_o^T + w
    cvt_split<<<(MROWS * DMODEL) / 1024, 256>>>(avp, Ah, Al, MROWS * DMODEL);
    cvt_split<<<(DMODEL * DMODEL) / 1024, 256>>>(Wo, Bh, Bl, DMODEL * DMODEL);
    mma_gemm<<<dim3(DMODEL / 128, MROWS / 128), 256, GEMM_SMEM>>>(
        Ah, Al, Bh, Bl, w, xp, DMODEL, DMODEL);

    // 6) LayerNorm -> out
    ln_kernel<<<MROWS, 256>>>(xp, gamma, beta, out);
}

// round 10
// speedup vs baseline: 3.5075x; 3.5075x over previous
#include <cuda_runtime.h>
#include <cuda_bf16.h>
#include <math.h>
#include <stdint.h>

#define QLEN   1024
#define BSZ    4
#define DMODEL 1024
#define NHEAD  16
#define GHEADS 2
#define DHEAD  64
#define QKD    128
#define QKVOUT 1280
#define MROWS  4096
#define SCALE  0.125f
#define LN_EPS 1e-5f

// ---------------- scratch (device globals; no allocations allowed) ----------
__device__ float g_wheads[MROWS * QKVOUT];
__device__ float g_rk[QLEN * QKD];
__device__ float g_AC[BSZ * GHEADS * QLEN * QLEN];
__device__ float g_BD[BSZ * GHEADS * QLEN * QLEN];
__device__ float g_avec[MROWS * DMODEL];
__device__ float g_x[MROWS * DMODEL];

__device__ __nv_bfloat16 g_bfA_hi[MROWS * DMODEL];
__device__ __nv_bfloat16 g_bfA_lo[MROWS * DMODEL];
__device__ __nv_bfloat16 g_bfB_hi[QKVOUT * DMODEL];
__device__ __nv_bfloat16 g_bfB_lo[QKVOUT * DMODEL];

// probability matrices (normalized), hi/lo split: [b][h][i][j]
__device__ __nv_bfloat16 g_Phi[BSZ * NHEAD * QLEN * QLEN];   // 134 MB
__device__ __nv_bfloat16 g_Plo[BSZ * NHEAD * QLEN * QLEN];   // 134 MB
// V transposed: [b][h][d][j] hi/lo
__device__ __nv_bfloat16 g_Vthi[BSZ * NHEAD * DHEAD * QLEN];
__device__ __nv_bfloat16 g_Vtlo[BSZ * NHEAD * DHEAD * QLEN];

// ---------------- helpers ----------------------------------------------------
__device__ __forceinline__ uint32_t smem_u32(const void* p) {
    uint32_t a;
    asm("{ .reg .u64 t; cvta.to.shared.u64 t, %1; cvt.u32.u64 %0, t; }"
        : "=r"(a) : "l"(p));
    return a;
}
__device__ __forceinline__ void ldm4(uint32_t* r, uint32_t addr) {
    asm volatile("ldmatrix.sync.aligned.m8n8.x4.shared.b16 {%0,%1,%2,%3}, [%4];"
                 : "=r"(r[0]), "=r"(r[1]), "=r"(r[2]), "=r"(r[3]) : "r"(addr));
}
__device__ __forceinline__ void mma16816(float* c, const uint32_t* a,
                                         uint32_t b0, uint32_t b1) {
    asm volatile(
        "mma.sync.aligned.m16n8k16.row.col.f32.bf16.bf16.f32 "
        "{%0,%1,%2,%3}, {%4,%5,%6,%7}, {%8,%9}, {%0,%1,%2,%3};"
        : "+f"(c[0]), "+f"(c[1]), "+f"(c[2]), "+f"(c[3])
        : "r"(a[0]), "r"(a[1]), "r"(a[2]), "r"(a[3]), "r"(b0), "r"(b1));
}
__device__ __forceinline__ void cp16(uint32_t saddr, const void* gaddr) {
    asm volatile("cp.async.cg.shared.global [%0], [%1], 16;\n"
                 :: "r"(saddr), "l"(gaddr) : "memory");
}

// ---------------- fp32 -> bf16 hi/lo split ----------------------------------
__global__ void __launch_bounds__(256) cvt_split(
    const float* __restrict__ x, __nv_bfloat16* __restrict__ hi,
    __nv_bfloat16* __restrict__ lo, int n)
{
    int i = (blockIdx.x * 256 + threadIdx.x) * 4;
    if (i >= n) return;
    float4 v = *(const float4*)(x + i);
    union { __nv_bfloat16 b[4]; uint2 u; } H, L;
    H.b[0] = __float2bfloat16_rn(v.x);
    H.b[1] = __float2bfloat16_rn(v.y);
    H.b[2] = __float2bfloat16_rn(v.z);
    H.b[3] = __float2bfloat16_rn(v.w);
    L.b[0] = __float2bfloat16_rn(v.x - __bfloat162float(H.b[0]));
    L.b[1] = __float2bfloat16_rn(v.y - __bfloat162float(H.b[1]));
    L.b[2] = __float2bfloat16_rn(v.z - __bfloat162float(H.b[2]));
    L.b[3] = __float2bfloat16_rn(v.w - __bfloat162float(H.b[3]));
    *(uint2*)(hi + i) = H.u;
    *(uint2*)(lo + i) = L.u;
}

// ---------------- HMMA split-bf16 NT GEMM, cp.async double-buffered ---------
#define LDSB  40
#define TILEE (128 * LDSB)
#define GEMM_SMEM (2 * 4 * TILEE * 2)

__global__ void __launch_bounds__(256) mma_gemm(
    const __nv_bfloat16* __restrict__ Ahi, const __nv_bfloat16* __restrict__ Alo,
    const __nv_bfloat16* __restrict__ Bhi, const __nv_bfloat16* __restrict__ Blo,
    const float* __restrict__ Dres, float* __restrict__ C, int N_, int K)
{
    extern __shared__ __nv_bfloat16 gsm[];
    const uint32_t sbase = smem_u32(gsm);

    const int t = threadIdx.x;
    const int warp = t >> 5, lane = t & 31;
    const int wm = warp >> 2, wn = warp & 3;
    const int m0 = blockIdx.y * 128, n0 = blockIdx.x * 128;

    float acc[4][4][4];
    #pragma unroll
    for (int i = 0; i < 4; i++)
        #pragma unroll
        for (int j = 0; j < 4; j++)
            #pragma unroll
            for (int u = 0; u < 4; u++) acc[i][j][u] = 0.f;

    const int lrow = t >> 2;
    const int lseg = (t & 3) * 8;

    const __nv_bfloat16* mat[4];
    mat[0] = Ahi + (size_t)m0 * K;
    mat[1] = Alo + (size_t)m0 * K;
    mat[2] = Bhi + (size_t)n0 * K;
    mat[3] = Blo + (size_t)n0 * K;

    const uint32_t so_b = ((uint32_t)lrow * LDSB + lseg) * 2;
    const uint32_t so_b2 = so_b + (uint32_t)64 * LDSB * 2;

    const uint32_t a_lane =
        ((uint32_t)(wm * 64 + (lane & 15)) * LDSB + (lane >> 4) * 8) * 2;
    const uint32_t b_lane =
        ((uint32_t)(wn * 32 + (lane & 7) + (lane >> 4) * 8) * LDSB +
         ((lane >> 3) & 1) * 8) * 2;

    const int NCH = K >> 5;

    #pragma unroll
    for (int mi = 0; mi < 4; mi++) {
        const uint32_t mb = sbase + (uint32_t)mi * TILEE * 2;
        cp16(mb + so_b,  mat[mi] + (size_t)lrow * K + lseg);
        cp16(mb + so_b2, mat[mi] + (size_t)(lrow + 64) * K + lseg);
    }
    asm volatile("cp.async.commit_group;\n");

    for (int c = 0; c < NCH; c++) {
        if (c + 1 < NCH) {
            const int k0 = (c + 1) << 5;
            const uint32_t stoff = (uint32_t)(((c + 1) & 1) * 4) * TILEE * 2;
            #pragma unroll
            for (int mi = 0; mi < 4; mi++) {
                const uint32_t mb = sbase + stoff + (uint32_t)mi * TILEE * 2;
                cp16(mb + so_b,  mat[mi] + (size_t)lrow * K + k0 + lseg);
                cp16(mb + so_b2, mat[mi] + (size_t)(lrow + 64) * K + k0 + lseg);
            }
            asm volatile("cp.async.commit_group;\n");
            asm volatile("cp.async.wait_group 1;\n");
        } else {
            asm volatile("cp.async.wait_group 0;\n");
        }
        __syncthreads();

        const uint32_t stoff = (uint32_t)((c & 1) * 4) * TILEE * 2;
        const uint32_t bAh = sbase + stoff;
        const uint32_t bAl = bAh + TILEE * 2;
        const uint32_t bBh = bAl + TILEE * 2;
        const uint32_t bBl = bBh + TILEE * 2;

        #pragma unroll
        for (int s = 0; s < 2; s++) {
            const uint32_t ko = s * 32;
            uint32_t ah[4][4], al[4][4], bh[2][4], bl[2][4];
            #pragma unroll
            for (int mf = 0; mf < 4; mf++) {
                ldm4(ah[mf], bAh + a_lane + mf * 1280 + ko);
                ldm4(al[mf], bAl + a_lane + mf * 1280 + ko);
            }
            #pragma unroll
            for (int np = 0; np < 2; np++) {
                ldm4(bh[np], bBh + b_lane + np * 1280 + ko);
                ldm4(bl[np], bBl + b_lane + np * 1280 + ko);
            }
            #pragma unroll
            for (int mf = 0; mf < 4; mf++) {
                #pragma unroll
                for (int nf = 0; nf < 4; nf++) {
                    const int np = nf >> 1, h = (nf & 1) * 2;
                    mma16816(acc[mf][nf], ah[mf], bh[np][h], bh[np][h + 1]);
                    mma16816(acc[mf][nf], ah[mf], bl[np][h], bl[np][h + 1]);
                    mma16816(acc[mf][nf], al[mf], bh[np][h], bh[np][h + 1]);
                }
            }
        }
        __syncthreads();
    }

    const int crow0 = m0 + wm * 64 + (lane >> 2);
    const int ccol0 = n0 + wn * 32 + (lane & 3) * 2;
    #pragma unroll
    for (int mf = 0; mf < 4; mf++) {
        #pragma unroll
        for (int nf = 0; nf < 4; nf++) {
            const int gr = crow0 + mf * 16;
            const int gc = ccol0 + nf * 8;
            float2 v0 = make_float2(acc[mf][nf][0], acc[mf][nf][1]);
            float2 v1 = make_float2(acc[mf][nf][2], acc[mf][nf][3]);
            if (Dres) {
                float2 d0 = *(const float2*)(Dres + (size_t)gr * N_ + gc);
                float2 d1 = *(const float2*)(Dres + (size_t)(gr + 8) * N_ + gc);
                v0.x += d0.x; v0.y += d0.y;
                v1.x += d1.x; v1.y += d1.y;
            }
            *(float2*)(C + (size_t)gr * N_ + gc) = v0;
            *(float2*)(C + (size_t)(gr + 8) * N_ + gc) = v1;
        }
    }
}

// ---------------- AC / BD batched GEMM (K=64, fp32 FFMA) --------------------
__global__ void __launch_bounds__(256) acbd_kernel(
    const float* __restrict__ wheads, const float* __restrict__ rk,
    const float* __restrict__ bias, float* __restrict__ Cbase, int mode)
{
    __shared__ float As[16][132];
    __shared__ float Bs[16][132];
    const int bg = blockIdx.z;
    const int b = bg >> 1, g = bg & 1;
    const int bx = blockIdx.x, by = blockIdx.y;
    const int t  = threadIdx.x;
    const int tx = t & 15, ty = t >> 4;

    const float* Aoff = wheads + b * QKVOUT + g * 64;
    const float* Boff = mode ? (rk + g * 64)
                             : (wheads + b * QKVOUT + QKD + g * 64);
    const int lda = BSZ * QKVOUT;
    const int ldb = mode ? QKD : (BSZ * QKVOUT);
    const float* bb = bias + g * 64;

    float acc[8][8];
    #pragma unroll
    for (int i = 0; i < 8; i++)
        #pragma unroll
        for (int j = 0; j < 8; j++) acc[i][j] = 0.f;

    const int lrow = t >> 2;
    const int lk4  = (t & 3) * 4;

    for (int k0 = 0; k0 < 64; k0 += 16) {
        float4 bias4 = *(const float4*)(bb + k0 + lk4);
        #pragma unroll
        for (int rr = 0; rr < 2; rr++) {
            int m = lrow + rr * 64;
            int gm = by * 128 + m;
            float4 a = *(const float4*)(Aoff + (size_t)gm * lda + k0 + lk4);
            As[lk4 + 0][m] = a.x + bias4.x; As[lk4 + 1][m] = a.y + bias4.y;
            As[lk4 + 2][m] = a.z + bias4.z; As[lk4 + 3][m] = a.w + bias4.w;
            int gn = bx * 128 + m;
            float4 bv = *(const float4*)(Boff + (size_t)gn * ldb + k0 + lk4);
            Bs[lk4 + 0][m] = bv.x; Bs[lk4 + 1][m] = bv.y;
            Bs[lk4 + 2][m] = bv.z; Bs[lk4 + 3][m] = bv.w;
        }
        __syncthreads();
        #pragma unroll
        for (int kk = 0; kk < 16; kk++) {
            float ar[8], br[8];
            #pragma unroll
            for (int u = 0; u < 8; u++) ar[u] = As[kk][ty * 8 + u];
            #pragma unroll
            for (int u = 0; u < 8; u++) br[u] = Bs[kk][tx * 8 + u];
            #pragma unroll
            for (int i = 0; i < 8; i++)
                #pragma unroll
                for (int j = 0; j < 8; j++) acc[i][j] += ar[i] * br[j];
        }
        __syncthreads();
    }
    float* C = Cbase + (size_t)bg * QLEN * QLEN;
    const int mbase = by * 128 + ty * 8;
    const int nbase = bx * 128 + tx * 8;
    #pragma unroll
    for (int i = 0; i < 8; i++) {
        size_t roff = (size_t)(mbase + i) * QLEN + nbase;
        #pragma unroll
        for (int j0 = 0; j0 < 8; j0 += 4) {
            float4 o;
            o.x = acc[i][j0 + 0]; o.y = acc[i][j0 + 1];
            o.z = acc[i][j0 + 2]; o.w = acc[i][j0 + 3];
            *(float4*)(C + roff + j0) = o;
        }
    }
}

// ---------------- score + rel_shift + mask + softmax -> normalized P --------
// block = (i, b); 256 threads; all 16 heads computed from one read of
// AC/BD/masks. Writes normalized probabilities as bf16 hi/lo.
#define SC_SMEM (16 * 1024 * 4)

__global__ void __launch_bounds__(256) score_kernel(
    const float* __restrict__ AC, const float* __restrict__ BD,
    const float* __restrict__ masks, const float* __restrict__ mproj,
    __nv_bfloat16* __restrict__ Phi, __nv_bfloat16* __restrict__ Plo)
{
    extern __shared__ float S[];              // [16][1024]
    const int i = blockIdx.x, b = blockIdx.y;
    const int t = threadIdx.x;
    const int warp = t >> 5, lane = t & 31;

    float mp0[16], mp1[16], mp2[16];
    #pragma unroll
    for (int h = 0; h < 16; h++) {
        mp0[h] = mproj[h];
        mp1[h] = mproj[16 + h];
        mp2[h] = mproj[32 + h];
    }

    const float* ac0r = AC + ((size_t)(b * 2 + 0) * QLEN + i) * QLEN;
    const float* ac1r = AC + ((size_t)(b * 2 + 1) * QLEN + i) * QLEN;
    const float* bd0b = BD + (size_t)(b * 2 + 0) * QLEN * QLEN;
    const float* bd1b = BD + (size_t)(b * 2 + 1) * QLEN * QLEN;

    #pragma unroll
    for (int k = 0; k < 4; k++) {
        const int j = t + k * 256;
        float ac0 = ac0r[j], ac1 = ac1r[j];
        unsigned s  = (unsigned)(i + 1) * 1024u + (unsigned)j;
        unsigned i2 = s / 1025u;
        unsigned j2 = s - i2 * 1025u;
        float bd0 = 0.f, bd1 = 0.f;
        if (j2) {
            bd0 = bd0b[(size_t)i2 * QLEN + (j2 - 1u)];
            bd1 = bd1b[(size_t)i2 * QLEN + (j2 - 1u)];
        }
        const float* mr = masks + ((size_t)i * QLEN + j) * 3;
        float m0 = mr[0], m1 = mr[1], m2 = mr[2];
        float base0 = (ac0 + bd0) * SCALE;
        float base1 = (ac1 + bd1) * SCALE;
        #pragma unroll
        for (int h = 0; h < 8; h++) {
            float mw = m0 * mp0[h] + m1 * mp1[h] + m2 * mp2[h];
            S[h * 1024 + j] = base0 * mw;
        }
        #pragma unroll
        for (int h = 8; h < 16; h++) {
            float mw = m0 * mp0[h] + m1 * mp1[h] + m2 * mp2[h];
            S[h * 1024 + j] = base1 * mw;
        }
    }
    __syncthreads();

    // warp w -> heads 2w, 2w+1; full-row softmax + normalize + hi/lo write
    #pragma unroll
    for (int hh = 0; hh < 2; hh++) {
        const int h = warp * 2 + hh;
        float* Sh = S + h * 1024;
        float mx = -1e30f;
        #pragma unroll 8
        for (int j = lane; j < 1024; j += 32) mx = fmaxf(mx, Sh[j]);
        #pragma unroll
        for (int o = 16; o > 0; o >>= 1)
            mx = fmaxf(mx, __shfl_xor_sync(0xffffffffu, mx, o));
        float sum = 0.f;
        #pragma unroll 8
        for (int j = lane; j < 1024; j += 32) {
            float e = __expf(Sh[j] - mx);
            Sh[j] = e;
            sum += e;
        }
        #pragma unroll
        for (int o = 16; o > 0; o >>= 1)
            sum += __shfl_xor_sync(0xffffffffu, sum, o);
        const float inv = 1.f / sum;
        __nv_bfloat16* ph = Phi + ((size_t)(b * 16 + h) * QLEN + i) * QLEN;
        __nv_bfloat16* pl = Plo + ((size_t)(b * 16 + h) * QLEN + i) * QLEN;
        #pragma unroll 8
        for (int j = lane; j < 1024; j += 32) {
            float p = Sh[j] * inv;
            __nv_bfloat16 hi = __float2bfloat16_rn(p);
            ph[j] = hi;
            pl[j] = __float2bfloat16_rn(p - __bfloat162float(hi));
        }
    }
}

// ---------------- V transpose-convert: wheads -> Vt[b][h][d][j] bf16 --------
__global__ void __launch_bounds__(256) cvt_vt(
    const float* __restrict__ wheads,
    __nv_bfloat16* __restrict__ Vthi, __nv_bfloat16* __restrict__ Vtlo)
{
    __shared__ float sm[64 * 33];
    const int bh = blockIdx.y;
    const int b = bh >> 4, h = bh & 15;
    const int j0 = blockIdx.x * 32;
    const int t = threadIdx.x;

    #pragma unroll
    for (int k = 0; k < 8; k++) {
        int idx = t + k * 256;               // 0..2047 = 32 j x 64 d
        int j = idx >> 6, d = idx & 63;
        sm[d * 33 + j] = wheads[(size_t)(j0 + j) * (BSZ * QKVOUT) +
                                b * QKVOUT + 2 * QKD + h * 64 + d];
    }
    __syncthreads();
    #pragma unroll
    for (int k = 0; k < 8; k++) {
        int idx = t + k * 256;
        int d = idx >> 5, j = idx & 31;
        float v = sm[d * 33 + j];
        __nv_bfloat16 hi = __float2bfloat16_rn(v);
        size_t o = ((size_t)(bh * 64 + d)) * QLEN + j0 + j;
        Vthi[o] = hi;
        Vtlo[o] = __float2bfloat16_rn(v - __bfloat162float(hi));
    }
}

// ---------------- PV GEMM: avec[i,d] = sum_j P[i,j] * Vt[d,j] ---------------
// per (b,h): M=1024, N=64, K=1024; BM=128, BN=64, BK=32; 256 thr,
// 8 warps 4m x 2n, warp tile 32x32. 3-term hi/lo split. P already normalized.
#define PV_TILEA (128 * LDSB)
#define PV_TILEB (64 * LDSB)
#define PV_STAGE (2 * PV_TILEA + 2 * PV_TILEB)
#define PV_SMEM  (2 * PV_STAGE * 2)

__global__ void __launch_bounds__(256) pv_gemm(
    const __nv_bfloat16* __restrict__ Phi, const __nv_bfloat16* __restrict__ Plo,
    const __nv_bfloat16* __restrict__ Vthi, const __nv_bfloat16* __restrict__ Vtlo,
    float* __restrict__ avec)
{
    extern __shared__ __nv_bfloat16 psm[];
    const uint32_t sbase = smem_u32(psm);
    const int bh = blockIdx.y;
    const int b = bh >> 4, h = bh & 15;
    const int i0 = blockIdx.x * 128;
    const int t = threadIdx.x;
    const int warp = t >> 5, lane = t & 31;
    const int wm = warp >> 1, wn = warp & 1;

    float acc[2][4][4];
    #pragma unroll
    for (int i = 0; i < 2; i++)
        #pragma unroll
        for (int j = 0; j < 4; j++)
            #pragma unroll
            for (int u = 0; u < 4; u++) acc[i][j][u] = 0.f;

    const __nv_bfloat16* pA[2];
    pA[0] = Phi + ((size_t)bh * QLEN + i0) * QLEN;
    pA[1] = Plo + ((size_t)bh * QLEN + i0) * QLEN;
    const __nv_bfloat16* pB[2];
    pB[0] = Vthi + (size_t)bh * 64 * QLEN;
    pB[1] = Vtlo + (size_t)bh * 64 * QLEN;

    const int arow = t >> 1;                 // 0..127
    const int aoff = (t & 1) * 16;           // bf16 offset in BK=32
    const int vrow = (t & 127) >> 1;         // 0..63
    const int voff = (t & 1) * 16;

    const uint32_t a_lane =
        ((uint32_t)(wm * 32 + (lane & 15)) * LDSB + (lane >> 4) * 8) * 2;
    const uint32_t b_lane =
        ((uint32_t)(wn * 32 + (lane & 7) + (lane >> 4) * 8) * LDSB +
         ((lane >> 3) & 1) * 8) * 2;

    // prologue stage 0
    {
        #pragma unroll
        for (int m = 0; m < 2; m++) {
            const uint32_t mb = sbase + (uint32_t)(m * PV_TILEA) * 2;
            const uint32_t so = ((uint32_t)arow * LDSB + aoff) * 2;
            cp16(mb + so,      pA[m] + (size_t)arow * QLEN + aoff);
            cp16(mb + so + 16, pA[m] + (size_t)arow * QLEN + aoff + 8);
        }
        if (t < 128) {
            #pragma unroll
            for (int m = 0; m < 2; m++) {
                const uint32_t mb = sbase +
                    (uint32_t)(2 * PV_TILEA + m * PV_TILEB) * 2;
                const uint32_t so = ((uint32_t)vrow * LDSB + voff) * 2;
                cp16(mb + so,      pB[m] + (size_t)vrow * QLEN + voff);
                cp16(mb + so + 16, pB[m] + (size_t)vrow * QLEN + voff + 8);
            }
        }
        asm volatile("cp.async.commit_group;\n");
    }

    const int NCH = QLEN >> 5;               // 32
    for (int c = 0; c < NCH; c++) {
        if (c + 1 < NCH) {
            const int k0 = (c + 1) << 5;
            const uint32_t stoff = (uint32_t)(((c + 1) & 1) * PV_STAGE) * 2;
            #pragma unroll
            for (int m = 0; m < 2; m++) {
                const uint32_t mb = sbase + stoff + (uint32_t)(m * PV_TILEA) * 2;
                const uint32_t so = ((uint32_t)arow * LDSB + aoff) * 2;
                cp16(mb + so,      pA[m] + (size_t)arow * QLEN + k0 + aoff);
                cp16(mb + so + 16, pA[m] + (size_t)arow * QLEN + k0 + aoff + 8);
            }
            if (t < 128) {
                #pragma unroll
                for (int m = 0; m < 2; m++) {
                    const uint32_t mb = sbase + stoff +
                        (uint32_t)(2 * PV_TILEA + m * PV_TILEB) * 2;
                    const uint32_t so = ((uint32_t)vrow * LDSB + voff) * 2;
                    cp16(mb + so,      pB[m] + (size_t)vrow * QLEN + k0 + voff);
                    cp16(mb + so + 16, pB[m] + (size_t)vrow * QLEN + k0 + voff + 8);
                }
            }
            asm volatile("cp.async.commit_group;\n");
            asm volatile("cp.async.wait_group 1;\n");
        } else {
            asm volatile("cp.async.wait_group 0;\n");
        }
        __syncthreads();

        const uint32_t stoff = (uint32_t)((c & 1) * PV_STAGE) * 2;
        const uint32_t bPh = sbase + stoff;
        const uint32_t bPl = bPh + (uint32_t)PV_TILEA * 2;
        const uint32_t bVh = bPl + (uint32_t)PV_TILEA * 2;
        const uint32_t bVl = bVh + (uint32_t)PV_TILEB * 2;

        #pragma unroll
        for (int s = 0; s < 2; s++) {
            const uint32_t ko = s * 32;
            uint32_t ah[2][4], al[2][4], vh[2][4], vl[2][4];
            #pragma unroll
            for (int mf = 0; mf < 2; mf++) {
                ldm4(ah[mf], bPh + a_lane + mf * 1280 + ko);
                ldm4(al[mf], bPl + a_lane + mf * 1280 + ko);
            }
            #pragma unroll
            for (int np = 0; np < 2; np++) {
                ldm4(vh[np], bVh + b_lane + np * 1280 + ko);
                ldm4(vl[np], bVl + b_lane + np * 1280 + ko);
            }
            #pragma unroll
            for (int mf = 0; mf < 2; mf++) {
                #pragma unroll
                for (int nf = 0; nf < 4; nf++) {
                    const int np = nf >> 1, hb = (nf & 1) * 2;
                    mma16816(acc[mf][nf], ah[mf], vh[np][hb], vh[np][hb + 1]);
                    mma16816(acc[mf][nf], ah[mf], vl[np][hb], vl[np][hb + 1]);
                    mma16816(acc[mf][nf], al[mf], vh[np][hb], vh[np][hb + 1]);
                }
            }
        }
        __syncthreads();
    }

    // epilogue: avec[((i*4+b)*16+h)*64 + d]
    const int rloc0 = wm * 32 + (lane >> 2);
    const int col0  = wn * 32 + (lane & 3) * 2;
    #pragma unroll
    for (int mf = 0; mf < 2; mf++) {
        #pragma unroll
        for (int nf = 0; nf < 4; nf++) {
            const int gr0 = i0 + rloc0 + mf * 16;
            const int gc  = col0 + nf * 8;
            float* o0 = avec + ((size_t)(gr0 * BSZ + b) * NHEAD + h) * 64 + gc;
            float* o1 = avec + ((size_t)((gr0 + 8) * BSZ + b) * NHEAD + h) * 64 + gc;
            *(float2*)o0 = make_float2(acc[mf][nf][0], acc[mf][nf][1]);
            *(float2*)o1 = make_float2(acc[mf][nf][2], acc[mf][nf][3]);
        }
    }
}

// ---------------- LayerNorm --------------------------------------------------
__global__ void __launch_bounds__(256) ln_kernel(
    const float* __restrict__ X, const float* __restrict__ gamma,
    const float* __restrict__ beta, float* __restrict__ out)
{
    const int row = blockIdx.x;
    const int t = threadIdx.x;
    const float4* x4 = (const float4*)(X + (size_t)row * DMODEL);
    float4 v = x4[t];
    float s  = v.x + v.y + v.z + v.w;
    float sq = v.x * v.x + v.y * v.y + v.z * v.z + v.w * v.w;
    #pragma unroll
    for (int o = 16; o > 0; o >>= 1) {
        s  += __shfl_xor_sync(0xffffffffu, s,  o);
        sq += __shfl_xor_sync(0xffffffffu, sq, o);
    }
    __shared__ float ssum[8], ssq[8];
    __shared__ float smu, srstd;
    if ((t & 31) == 0) { ssum[t >> 5] = s; ssq[t >> 5] = sq; }
    __syncthreads();
    if (t == 0) {
        float ts = 0.f, tq = 0.f;
        #pragma unroll
        for (int k = 0; k < 8; k++) { ts += ssum[k]; tq += ssq[k]; }
        float mu = ts * (1.f / DMODEL);
        float var = tq * (1.f / DMODEL) - mu * mu;
        smu = mu;
        srstd = rsqrtf(var + LN_EPS);
    }
    __syncthreads();
    float mu = smu, rstd = srstd;
    float4 gm = ((const float4*)gamma)[t];
    float4 bt = ((const float4*)beta)[t];
    float4 o;
    o.x = (v.x - mu) * rstd * gm.x + bt.x;
    o.y = (v.y - mu) * rstd * gm.y + bt.y;
    o.z = (v.z - mu) * rstd * gm.z + bt.z;
    o.w = (v.w - mu) * rstd * gm.w + bt.w;
    ((float4*)(out + (size_t)row * DMODEL))[t] = o;
}

// ---------------- launch ----------------------------------------------------
extern "C" void kernel_launch(void* const* d_in, const int* in_sizes, int n_in,
                              void* d_out, int out_size)
{
    const float* w     = (const float*)d_in[0];
    const float* r     = (const float*)d_in[1];
    const float* rwb   = (const float*)d_in[2];
    const float* rrb   = (const float*)d_in[3];
    const float* masks = (const float*)d_in[4];
    const float* Wqkv  = (const float*)d_in[5];
    const float* Wr    = (const float*)d_in[6];
    const float* mproj = (const float*)d_in[7];
    const float* Wo    = (const float*)d_in[8];
    const float* gamma = (const float*)d_in[9];
    const float* beta  = (const float*)d_in[10];
    float* out = (float*)d_out;

    float *wheads, *rkp, *acp, *bdp, *avp, *xp;
    cudaGetSymbolAddress((void**)&wheads, g_wheads);
    cudaGetSymbolAddress((void**)&rkp,    g_rk);
    cudaGetSymbolAddress((void**)&acp,    g_AC);
    cudaGetSymbolAddress((void**)&bdp,    g_BD);
    cudaGetSymbolAddress((void**)&avp,    g_avec);
    cudaGetSymbolAddress((void**)&xp,     g_x);

    __nv_bfloat16 *Ah, *Al, *Bh, *Bl, *Phi, *Plo, *Vth, *Vtl;
    cudaGetSymbolAddress((void**)&Ah,  g_bfA_hi);
    cudaGetSymbolAddress((void**)&Al,  g_bfA_lo);
    cudaGetSymbolAddress((void**)&Bh,  g_bfB_hi);
    cudaGetSymbolAddress((void**)&Bl,  g_bfB_lo);
    cudaGetSymbolAddress((void**)&Phi, g_Phi);
    cudaGetSymbolAddress((void**)&Plo, g_Plo);
    cudaGetSymbolAddress((void**)&Vth, g_Vthi);
    cudaGetSymbolAddress((void**)&Vtl, g_Vtlo);

    cudaFuncSetAttribute(mma_gemm,
                         cudaFuncAttributeMaxDynamicSharedMemorySize, GEMM_SMEM);
    cudaFuncSetAttribute(score_kernel,
                         cudaFuncAttributeMaxDynamicSharedMemorySize, SC_SMEM);
    cudaFuncSetAttribute(pv_gemm,
                         cudaFuncAttributeMaxDynamicSharedMemorySize, PV_SMEM);

    // 1) w_heads = w @ W_qkv^T
    cvt_split<<<(MROWS * DMODEL) / 1024, 256>>>(w, Ah, Al, MROWS * DMODEL);
    cvt_split<<<(QKVOUT * DMODEL) / 1024, 256>>>(Wqkv, Bh, Bl, QKVOUT * DMODEL);
    mma_gemm<<<dim3(QKVOUT / 128, MROWS / 128), 256, GEMM_SMEM>>>(
        Ah, Al, Bh, Bl, nullptr, wheads, QKVOUT, DMODEL);

    // 2) r_head_k = r @ W_r^T
    cvt_split<<<(QLEN * DMODEL) / 1024, 256>>>(r, Ah, Al, QLEN * DMODEL);
    cvt_split<<<(QKD * DMODEL) / 1024, 256>>>(Wr, Bh, Bl, QKD * DMODEL);
    mma_gemm<<<dim3(QKD / 128, QLEN / 128), 256, GEMM_SMEM>>>(
        Ah, Al, Bh, Bl, nullptr, rkp, QKD, DMODEL);

    // 3) AC, BD (pre-shift)
    acbd_kernel<<<dim3(8, 8, BSZ * GHEADS), 256>>>(wheads, rkp, rwb, acp, 0);
    acbd_kernel<<<dim3(8, 8, BSZ * GHEADS), 256>>>(wheads, rkp, rrb, bdp, 1);

    // 4a) scores + softmax -> normalized bf16 hi/lo P
    score_kernel<<<dim3(QLEN, BSZ), 256, SC_SMEM>>>(
        acp, bdp, masks, mproj, Phi, Plo);

    // 4b) V transpose-convert
    cvt_vt<<<dim3(QLEN / 32, BSZ * NHEAD), 256>>>(wheads, Vth, Vtl);

    // 4c) PV GEMM -> avec
    pv_gemm<<<dim3(QLEN / 128, BSZ * NHEAD), 256, PV_SMEM>>>(
        Phi, Plo, Vth, Vtl, avp);

    // 5) x = attn_vec @ W_o^T + w
    cvt_split<<<(MROWS * DMODEL) / 1024, 256>>>(avp, Ah, Al, MROWS * DMODEL);
    cvt_split<<<(DMODEL * DMODEL) / 1024, 256>>>(Wo, Bh, Bl, DMODEL * DMODEL);
    mma_gemm<<<dim3(DMODEL / 128, MROWS / 128), 256, GEMM_SMEM>>>(
        Ah, Al, Bh, Bl, w, xp, DMODEL, DMODEL);

    // 6) LayerNorm -> out
    ln_kernel<<<MROWS, 256>>>(xp, gamma, beta, out);
}